// round 7
// baseline (speedup 1.0000x reference)
#include <cuda_runtime.h>

#define NN 2048
#define NE 32768
#define DF 2048
#define TOPK 20
#define RMAXF 1e-5f
#define ROWS 4
#define NTILES (NN / ROWS)      // 512
#define NTHREADS 512
#define GRID 148
#define LISTCAP 512
#define TCAP 8192
#define MAXIT 500

// ---------------- device scratch ----------------
__device__ int g_rowptr[NN + 1], g_colptr[NN + 1];
__device__ float g_halfinv[NN];
__device__ int g_dst[NE];   // CSR out-edges (per-row sorted)
__device__ int g_src[NE];   // CSC in-edges  (per-col sorted)
__device__ int g_perm[NN];  // columns sorted by in-degree
__device__ int g_work;

// ---------------- merged single-block setup ----------------
__global__ void __launch_bounds__(1024) k_setup(const int* __restrict__ ei) {
    __shared__ int sdeg[NN], sindeg[NN], sfr[NN], sfc[NN];
    __shared__ int s[256];
    __shared__ int hist[64], hbase[64];
    const int t = threadIdx.x;
    const bool active = (t < 256);

    if (t == 0) g_work = 0;
    for (int k = t; k < NN; k += 1024) { sdeg[k] = 0; sindeg[k] = 0; sfr[k] = 0; sfc[k] = 0; }
    if (t < 64) hist[t] = 0;
    __syncthreads();

    // count degrees
    for (int e = t; e < NE; e += 1024) {
        atomicAdd(&sdeg[ei[e]], 1);
        atomicAdd(&sindeg[ei[NE + e]], 1);
    }
    __syncthreads();

    // prefix scans — ALL threads hit every barrier; work predicated on t<256
    for (int pass = 0; pass < 2; pass++) {
        const int* cnt = pass ? sdeg : sindeg;
        int* ptr = pass ? g_rowptr : g_colptr;
        int v[8]; int sum = 0; int base = t * 8;
        if (active) {
#pragma unroll
            for (int m = 0; m < 8; m++) { v[m] = cnt[base + m]; sum += v[m]; }
            s[t] = sum;
        }
        __syncthreads();
        for (int off = 1; off < 256; off <<= 1) {
            int x = (active && t >= off) ? s[t - off] : 0;
            __syncthreads();
            if (active) s[t] += x;
            __syncthreads();
        }
        if (active) {
            int excl = (t == 0) ? 0 : s[t - 1];
#pragma unroll
            for (int m = 0; m < 8; m++) { ptr[base + m] = excl; excl += v[m]; }
            if (t == 255) ptr[NN] = excl;
        }
        __syncthreads();
    }

    // halfinv + degree histogram
    for (int k = t; k < NN; k += 1024) {
        int d = sdeg[k];
        g_halfinv[k] = 0.5f / (d ? (float)d : 1.f);
        atomicAdd(&hist[min(sindeg[k], 63)], 1);
    }
    __syncthreads();
    if (t == 0) { int acc = 0; for (int b = 0; b < 64; b++) { hbase[b] = acc; acc += hist[b]; } }
    __syncthreads();
    for (int k = t; k < NN; k += 1024) {
        int pos = atomicAdd(&hbase[min(sindeg[k], 63)], 1);
        g_perm[pos] = k;
    }

    // fill CSR/CSC
    for (int e = t; e < NE; e += 1024) {
        int r = ei[e], c = ei[NE + e];
        int pr = atomicAdd(&sfr[r], 1);
        g_dst[g_rowptr[r] + pr] = c;
        int pc = atomicAdd(&sfc[c], 1);
        g_src[g_colptr[c] + pc] = r;
    }
    __syncthreads();

    // canonicalize list order (deterministic fp sums): insertion sort per list
    for (int id = t; id < 2 * NN; id += 1024) {
        int* arr; int p0, p1;
        if (id < NN) { arr = g_src; p0 = g_colptr[id]; p1 = g_colptr[id + 1]; }
        else { arr = g_dst; p0 = g_rowptr[id - NN]; p1 = g_rowptr[id - NN + 1]; }
        for (int i = p0 + 1; i < p1; i++) {
            int x = arr[i]; int j = i - 1;
            while (j >= p0 && arr[j] > x) { arr[j + 1] = arr[j]; j--; }
            arr[j + 1] = x;
        }
    }
}

// ---------------- persistent all-in-shared push + fused topk/output ----------------
__global__ void __launch_bounds__(NTHREADS, 1)
k_push(const float* __restrict__ X, float* __restrict__ out) {
    extern __shared__ float sh[];
    float* pv = sh;                               // [8192] masked push*(0.5/deg)
    float* cur = pv + ROWS * NN;                  // [8192] residual
    float* Pp = cur + ROWS * NN;                  // [8192] P accumulator
    float* shh = Pp + ROWS * NN;                  // [2048] 0.5/deg
    int* scol = (int*)(shh + NN);                 // [2052] CSC colptr
    int* lt = scol + NN + 4;                      // [TCAP] touched entries
    int* lk = lt + TCAP;                          // [LISTCAP] frontier entries
    float* lw = (float*)(lk + LISTCAP);           // [LISTCAP] frontier weights
    unsigned* sbits = (unsigned*)(lw + LISTCAP);  // [256] dedupe bitset
    unsigned short* ssrc = (unsigned short*)(sbits + 256);   // [NE] src<<4
    unsigned short* sperm = ssrc + NE;            // [NN] degree-sorted columns
    __shared__ int s_cnt, s_lc, s_tc, s_nc, s_tile;
    __shared__ float s_redv[16];
    __shared__ int s_redi[16];
    __shared__ float s_tv[ROWS][TOPK];
    __shared__ int s_ti[ROWS][TOPK];

    float4* pv4 = (float4*)pv;
    float4* cur4 = (float4*)cur;
    float4* Pp4 = (float4*)Pp;

    const int tid = threadIdx.x;
    const int lane = tid & 31;
    const int wid = tid >> 5;

    // ---- stage tile-invariant graph data once per CTA
    for (int k = tid; k < NN; k += NTHREADS) shh[k] = g_halfinv[k];
    for (int k = tid; k <= NN; k += NTHREADS) scol[k] = g_colptr[k];
    for (int e = tid; e < NE; e += NTHREADS) ssrc[e] = (unsigned short)(g_src[e] << 4);
    for (int k = tid; k < NN; k += NTHREADS) sperm[k] = (unsigned short)g_perm[k];

    while (true) {
        __syncthreads();
        if (tid == 0) s_tile = atomicAdd(&g_work, 1);
        __syncthreads();
        const int t = s_tile;
        if (t >= NTILES) break;
        const int row0 = t * ROWS;

        // ---- init tile state
#pragma unroll
        for (int m = 0; m < NN / NTHREADS; m++) {
            int j = tid + NTHREADS * m;
            float4 z = make_float4(0.f, 0.f, 0.f, 0.f);
            Pp4[j] = z;
            int d = j - row0;
            if (d >= 0 && d < ROWS) ((float*)&z)[d] = 1.f;
            cur4[j] = z;
        }

        int mode = 0;   // 0: run phase A; 1: frontier in lk/cnt is valid
        int cnt = 0;

        for (int iter = 0; iter < MAXIT; iter++) {
            if (mode == 0) {
                if (tid == 0) { s_cnt = 0; s_lc = 0; s_tc = 0; s_nc = 0; }
                for (int w = tid; w < 256; w += NTHREADS) sbits[w] = 0;
                __syncthreads();
                // ---- phase A: mask, snapshot pv, keep in cur, accumulate P, count
                int c = 0;
#pragma unroll
                for (int m = 0; m < NN / NTHREADS; m++) {
                    int j = tid + NTHREADS * m;
                    float4 v = cur4[j];
                    float h = shh[j];
                    bool px = v.x >= RMAXF, py = v.y >= RMAXF,
                         pz = v.z >= RMAXF, pw = v.w >= RMAXF;
                    pv4[j] = make_float4(px ? v.x * h : 0.f, py ? v.y * h : 0.f,
                                         pz ? v.z * h : 0.f, pw ? v.w * h : 0.f);
                    if (px | py | pz | pw) {
                        float4 p = Pp4[j];
                        if (px) { p.x += 0.5f * v.x; v.x = 0.f; c++; }
                        if (py) { p.y += 0.5f * v.y; v.y = 0.f; c++; }
                        if (pz) { p.z += 0.5f * v.z; v.z = 0.f; c++; }
                        if (pw) { p.w += 0.5f * v.w; v.w = 0.f; c++; }
                        Pp4[j] = p;
                        cur4[j] = v;
                    }
                }
                c = __reduce_add_sync(0xffffffffu, c);
                if (lane == 0 && c) atomicAdd(&s_cnt, c);
                __syncthreads();
                cnt = s_cnt;
                if (cnt == 0) break;

                if (cnt > LISTCAP) {
                    // ---- dense path: pure-LDS CSC gather
                    // equal-degree 32-col groups, dealt round-robin to warps
                    bool any = false;
#pragma unroll
                    for (int m = 0; m < NN / NTHREADS; m++) {
                        int grp = wid + (NTHREADS / 32) * m;   // 0..63
                        int jr = sperm[(grp << 5) + lane];
                        int p0 = scol[jr], p1 = scol[jr + 1];
                        float4 acc = cur4[jr];
#pragma unroll 4
                        for (int p = p0; p < p1; p++) {
                            float4 v = *(const float4*)((const char*)pv + ssrc[p]);
                            acc.x += v.x; acc.y += v.y; acc.z += v.z; acc.w += v.w;
                        }
                        cur4[jr] = acc;
                        any |= (acc.x >= RMAXF) | (acc.y >= RMAXF) |
                               (acc.z >= RMAXF) | (acc.w >= RMAXF);
                    }
                    if (!__syncthreads_or(any ? 1 : 0)) break;
                    continue;  // mode stays 0
                }
                // ---- sparse entry from phase A: build lk/lw from pv
#pragma unroll
                for (int m = 0; m < NN / NTHREADS; m++) {
                    int j = tid + NTHREADS * m;
                    float4 v = pv4[j];
#pragma unroll
                    for (int r = 0; r < 4; r++) {
                        float w = ((float*)&v)[r];
                        bool pr = w > 0.f;
                        unsigned msk = __ballot_sync(0xffffffffu, pr);
                        int base = 0;
                        if (lane == 0 && msk) base = atomicAdd(&s_lc, __popc(msk));
                        base = __shfl_sync(0xffffffffu, base, 0);
                        if (pr) {
                            int pos = base + __popc(msk & ((1u << lane) - 1));
                            lk[pos] = (j << 2) | r; lw[pos] = w;
                        }
                    }
                }
                __syncthreads();
            } else {
                // ---- list mode: process frontier directly (no scans)
                if (tid == 0) { s_tc = 0; s_nc = 0; }
                for (int w = tid; w < 256; w += NTHREADS) sbits[w] = 0;
                for (int l = tid; l < cnt; l += NTHREADS) {
                    int e = lk[l];
                    float v = cur[e];
                    Pp[e] += 0.5f * v;
                    lw[l] = v * shh[e >> 2];
                    cur[e] = 0.f;
                }
                __syncthreads();
            }

            // ---- scatter frontier via CSR, record touches
            for (int l = tid; l < cnt; l += NTHREADS) {
                int e = lk[l], k = e >> 2, r = e & 3;
                float w = lw[l];
                int p1 = g_rowptr[k + 1];
                for (int p = g_rowptr[k]; p < p1; p++) {
                    int d = (g_dst[p] << 2) | r;
                    atomicAdd(&cur[d], w);
                    int tp = atomicAdd(&s_tc, 1);
                    if (tp < TCAP) lt[tp] = d;
                }
            }
            __syncthreads();
            int tc = s_tc;
            if (tc > TCAP) { mode = 0; continue; }  // overflow: rebuild by phase A

            // ---- build next frontier from touched entries (bitset dedupe)
            for (int l = tid; l < tc; l += NTHREADS) {
                int e = lt[l];
                if (cur[e] >= RMAXF) {
                    unsigned bit = 1u << (e & 31);
                    unsigned old = atomicOr(&sbits[e >> 5], bit);
                    if (!(old & bit)) {
                        int pos = atomicAdd(&s_nc, 1);
                        if (pos < LISTCAP) lk[pos] = e;
                    }
                }
            }
            __syncthreads();
            int nc = s_nc;
            if (nc == 0) break;
            if (nc > LISTCAP) { mode = 0; }
            else { mode = 1; cnt = nc; }
        }
        __syncthreads();

        // ---- fused top-k per row (128 threads per row)
        const int rg = tid >> 7;
        const int tl = tid & 127;
        for (int q = 0; q < TOPK; q++) {
            float bv = -1.f; int bi = NN;
#pragma unroll
            for (int m = 0; m < NN / 128; m++) {
                int j = tl + 128 * m;
                float v = Pp[(j << 2) | rg];
                if (v > bv || (v == bv && j < bi)) { bv = v; bi = j; }
            }
#pragma unroll
            for (int off = 16; off; off >>= 1) {
                float ov = __shfl_down_sync(0xffffffffu, bv, off);
                int oi = __shfl_down_sync(0xffffffffu, bi, off);
                if (ov > bv || (ov == bv && oi < bi)) { bv = ov; bi = oi; }
            }
            if (lane == 0) { s_redv[wid] = bv; s_redi[wid] = bi; }
            __syncthreads();
            if (tl == 0) {
                float v0 = s_redv[4 * rg]; int i0 = s_redi[4 * rg];
#pragma unroll
                for (int w = 1; w < 4; w++) {
                    float v1 = s_redv[4 * rg + w]; int i1 = s_redi[4 * rg + w];
                    if (v1 > v0 || (v1 == v0 && i1 < i0)) { v0 = v1; i0 = i1; }
                }
                s_tv[rg][q] = v0; s_ti[rg][q] = i0;
                Pp[(i0 << 2) | rg] = -2.f;
            }
            __syncthreads();
        }

        // ---- output GEMV
        float tv[TOPK]; int ti[TOPK];
#pragma unroll
        for (int q = 0; q < TOPK; q++) {
            tv[q] = s_tv[rg][q];
            ti[q] = s_ti[rg][q] * (DF / 4);
        }
        const float4* X4 = (const float4*)X;
        float4* out4 = (float4*)out;
#pragma unroll
        for (int m = 0; m < DF / 4 / 128; m++) {
            int col = tl + 128 * m;
            float4 acc = make_float4(0.f, 0.f, 0.f, 0.f);
#pragma unroll
            for (int q = 0; q < TOPK; q++) {
                float w = tv[q];
                float4 x = __ldg(&X4[ti[q] + col]);
                acc.x += w * x.x; acc.y += w * x.y;
                acc.z += w * x.z; acc.w += w * x.w;
            }
            out4[(size_t)(row0 + rg) * (DF / 4) + col] = acc;
        }
    }
}

// ---------------- launch ----------------
extern "C" void kernel_launch(void* const* d_in, const int* in_sizes, int n_in,
                              void* d_out, int out_size) {
    const float* X;
    const int* ei;
    if (in_sizes[0] == 2 * NE) { ei = (const int*)d_in[0]; X = (const float*)d_in[1]; }
    else { X = (const float*)d_in[0]; ei = (const int*)d_in[1]; }
    float* out = (float*)d_out;

    const int smem = (3 * ROWS * NN + NN) * sizeof(float)        // pv,cur,Pp,shh
                   + (NN + 4 + TCAP + LISTCAP) * sizeof(int)     // scol,lt,lk
                   + LISTCAP * sizeof(float)                     // lw
                   + 256 * sizeof(unsigned)                      // sbits
                   + NE * sizeof(unsigned short)                 // ssrc
                   + NN * sizeof(unsigned short);                // sperm
    cudaFuncSetAttribute(k_push, cudaFuncAttributeMaxDynamicSharedMemorySize, smem);

    k_setup<<<1, 1024>>>(ei);
    k_push<<<GRID, NTHREADS, smem>>>(X, out);
}

// round 8
// speedup vs baseline: 1.2212x; 1.2212x over previous
#include <cuda_runtime.h>

#define NN 2048
#define NE 32768
#define DF 2048
#define TOPK 20
#define RMAXF 1e-5f
#define ROWS 4
#define NTILES (NN / ROWS)      // 512
#define NTHREADS 1024
#define GRID 148
#define LISTCAP 512
#define TCAP 8192
#define MAXIT 500

// ---------------- device scratch ----------------
__device__ int g_deg[NN], g_indeg[NN];
__device__ int g_rowptr[NN + 1], g_colptr[NN + 1];
__device__ int g_fillr[NN], g_fillc[NN];
__device__ float g_halfinv[NN];
__device__ int g_dst[NE];   // CSR out-edges (per-row sorted)
__device__ int g_src[NE];   // CSC in-edges  (per-col sorted)
__device__ int g_perm[NN];  // columns sorted by in-degree
__device__ int g_work;

// ---------------- graph build (multi-kernel: fast, ~30us total) ----------------
__global__ void k_zero() {
    int t = threadIdx.x;
    for (int k = t; k < NN; k += blockDim.x) {
        g_deg[k] = 0; g_indeg[k] = 0; g_fillr[k] = 0; g_fillc[k] = 0;
    }
    if (t == 0) g_work = 0;
}

__global__ void k_count(const int* __restrict__ ei) {
    int e = blockIdx.x * blockDim.x + threadIdx.x;
    if (e >= NE) return;
    atomicAdd(&g_deg[ei[e]], 1);
    atomicAdd(&g_indeg[ei[NE + e]], 1);
}

__global__ void k_scan() {
    __shared__ int s[256];
    int t = threadIdx.x;
    for (int pass = 0; pass < 2; pass++) {
        const int* cnt = pass ? g_deg : g_indeg;
        int* ptr = pass ? g_rowptr : g_colptr;
        int base = t * 8;
        int v[8]; int sum = 0;
#pragma unroll
        for (int m = 0; m < 8; m++) { v[m] = cnt[base + m]; sum += v[m]; }
        s[t] = sum; __syncthreads();
        for (int off = 1; off < 256; off <<= 1) {
            int x = (t >= off) ? s[t - off] : 0;
            __syncthreads();
            s[t] += x;
            __syncthreads();
        }
        int excl = (t == 0) ? 0 : s[t - 1];
#pragma unroll
        for (int m = 0; m < 8; m++) { ptr[base + m] = excl; excl += v[m]; }
        if (t == 255) ptr[NN] = excl;
        __syncthreads();
    }
    int base = t * 8;
#pragma unroll
    for (int m = 0; m < 8; m++) {
        int d = g_deg[base + m];
        g_halfinv[base + m] = 0.5f / (d ? (float)d : 1.f);
    }
}

__global__ void k_perm() {
    __shared__ int hist[64], base[64];
    int t = threadIdx.x;  // 256
    if (t < 64) hist[t] = 0;
    __syncthreads();
    for (int k = t; k < NN; k += 256) atomicAdd(&hist[min(g_indeg[k], 63)], 1);
    __syncthreads();
    if (t == 0) { int s = 0; for (int b = 0; b < 64; b++) { base[b] = s; s += hist[b]; } }
    __syncthreads();
    for (int k = t; k < NN; k += 256) {
        int pos = atomicAdd(&base[min(g_indeg[k], 63)], 1);
        g_perm[pos] = k;
    }
}

__global__ void k_fill(const int* __restrict__ ei) {
    int e = blockIdx.x * blockDim.x + threadIdx.x;
    if (e >= NE) return;
    int r = ei[e], c = ei[NE + e];
    int pr = atomicAdd(&g_fillr[r], 1);
    g_dst[g_rowptr[r] + pr] = c;
    int pc = atomicAdd(&g_fillc[c], 1);
    g_src[g_colptr[c] + pc] = r;
}

__device__ __forceinline__ void insort(int* a, int n) {
    for (int i = 1; i < n; i++) {
        int x = a[i]; int j = i - 1;
        while (j >= 0 && a[j] > x) { a[j + 1] = a[j]; j--; }
        a[j + 1] = x;
    }
}

__global__ void k_sort() {
    int id = blockIdx.x * blockDim.x + threadIdx.x;
    if (id >= 2 * NN) return;
    int* arr; int p0, p1;
    if (id < NN) { arr = g_src; p0 = g_colptr[id]; p1 = g_colptr[id + 1]; }
    else { arr = g_dst; p0 = g_rowptr[id - NN]; p1 = g_rowptr[id - NN + 1]; }
    int n = p1 - p0;
    if (n <= 1) return;
    if (n <= 160) {
        int buf[160];
        for (int i = 0; i < n; i++) buf[i] = arr[p0 + i];
        insort(buf, n);
        for (int i = 0; i < n; i++) arr[p0 + i] = buf[i];
    } else {
        insort(arr + p0, n);
    }
}

// ---------------- persistent all-in-shared push + fused topk/output ----------------
__global__ void __launch_bounds__(NTHREADS, 1)
k_push(const float* __restrict__ X, float* __restrict__ out) {
    extern __shared__ float sh[];
    float* pv = sh;                               // [8192] masked push*(0.5/deg)
    float* cur = pv + ROWS * NN;                  // [8192] residual
    float* Pp = cur + ROWS * NN;                  // [8192] P accumulator
    float* shh = Pp + ROWS * NN;                  // [2048] 0.5/deg
    int* scol = (int*)(shh + NN);                 // [2052] CSC colptr
    int* lt = scol + NN + 4;                      // [TCAP] touched entries
    int* lk = lt + TCAP;                          // [LISTCAP] frontier entries
    float* lw = (float*)(lk + LISTCAP);           // [LISTCAP] frontier weights
    unsigned* sbits = (unsigned*)(lw + LISTCAP);  // [256] dedupe bitset
    unsigned short* ssrc = (unsigned short*)(sbits + 256);   // [NE] src<<4
    unsigned short* sperm = ssrc + NE;            // [NN] degree-sorted columns
    __shared__ int s_cnt, s_lc, s_tc, s_nc, s_tile;
    __shared__ float s_redv[32];
    __shared__ int s_redi[32];
    __shared__ float s_tv[ROWS][TOPK];
    __shared__ int s_ti[ROWS][TOPK];

    float4* pv4 = (float4*)pv;
    float4* cur4 = (float4*)cur;
    float4* Pp4 = (float4*)Pp;

    const int tid = threadIdx.x;
    const int lane = tid & 31;
    const int wid = tid >> 5;

    // ---- stage tile-invariant graph data once per CTA
    for (int k = tid; k < NN; k += NTHREADS) shh[k] = g_halfinv[k];
    for (int k = tid; k <= NN; k += NTHREADS) scol[k] = g_colptr[k];
    for (int e = tid; e < NE; e += NTHREADS) ssrc[e] = (unsigned short)(g_src[e] << 4);
    for (int k = tid; k < NN; k += NTHREADS) sperm[k] = (unsigned short)g_perm[k];

    while (true) {
        __syncthreads();
        if (tid == 0) s_tile = atomicAdd(&g_work, 1);
        __syncthreads();
        const int t = s_tile;
        if (t >= NTILES) break;
        const int row0 = t * ROWS;

        // ---- init tile state
#pragma unroll
        for (int m = 0; m < NN / NTHREADS; m++) {
            int j = tid + NTHREADS * m;
            float4 z = make_float4(0.f, 0.f, 0.f, 0.f);
            Pp4[j] = z;
            int d = j - row0;
            if (d >= 0 && d < ROWS) ((float*)&z)[d] = 1.f;
            cur4[j] = z;
        }

        int mode = 0;   // 0: run phase A; 1: frontier in lk/cnt is valid
        int cnt = 0;

        for (int iter = 0; iter < MAXIT; iter++) {
            if (mode == 0) {
                if (tid == 0) { s_cnt = 0; s_lc = 0; s_tc = 0; s_nc = 0; }
                for (int w = tid; w < 256; w += NTHREADS) sbits[w] = 0;
                __syncthreads();
                // ---- phase A: mask, snapshot pv, keep in cur, accumulate P, count
                int c = 0;
#pragma unroll
                for (int m = 0; m < NN / NTHREADS; m++) {
                    int j = tid + NTHREADS * m;
                    float4 v = cur4[j];
                    float h = shh[j];
                    bool px = v.x >= RMAXF, py = v.y >= RMAXF,
                         pz = v.z >= RMAXF, pw = v.w >= RMAXF;
                    pv4[j] = make_float4(px ? v.x * h : 0.f, py ? v.y * h : 0.f,
                                         pz ? v.z * h : 0.f, pw ? v.w * h : 0.f);
                    if (px | py | pz | pw) {
                        float4 p = Pp4[j];
                        if (px) { p.x += 0.5f * v.x; v.x = 0.f; c++; }
                        if (py) { p.y += 0.5f * v.y; v.y = 0.f; c++; }
                        if (pz) { p.z += 0.5f * v.z; v.z = 0.f; c++; }
                        if (pw) { p.w += 0.5f * v.w; v.w = 0.f; c++; }
                        Pp4[j] = p;
                        cur4[j] = v;
                    }
                }
                c = __reduce_add_sync(0xffffffffu, c);
                if (lane == 0 && c) atomicAdd(&s_cnt, c);
                __syncthreads();
                cnt = s_cnt;
                if (cnt == 0) break;

                if (cnt > LISTCAP) {
                    // ---- dense path: pure-LDS CSC gather
                    bool any = false;
#pragma unroll
                    for (int m = 0; m < NN / NTHREADS; m++) {
                        int grp = wid + (NTHREADS / 32) * m;   // 0..63
                        int jr = sperm[(grp << 5) + lane];
                        int p0 = scol[jr], p1 = scol[jr + 1];
                        float4 acc = cur4[jr];
#pragma unroll 4
                        for (int p = p0; p < p1; p++) {
                            float4 v = *(const float4*)((const char*)pv + ssrc[p]);
                            acc.x += v.x; acc.y += v.y; acc.z += v.z; acc.w += v.w;
                        }
                        cur4[jr] = acc;
                        any |= (acc.x >= RMAXF) | (acc.y >= RMAXF) |
                               (acc.z >= RMAXF) | (acc.w >= RMAXF);
                    }
                    if (!__syncthreads_or(any ? 1 : 0)) break;
                    continue;  // mode stays 0
                }
                // ---- sparse entry from phase A: build lk/lw from pv
#pragma unroll
                for (int m = 0; m < NN / NTHREADS; m++) {
                    int j = tid + NTHREADS * m;
                    float4 v = pv4[j];
#pragma unroll
                    for (int r = 0; r < 4; r++) {
                        float w = ((float*)&v)[r];
                        bool pr = w > 0.f;
                        unsigned msk = __ballot_sync(0xffffffffu, pr);
                        int base = 0;
                        if (lane == 0 && msk) base = atomicAdd(&s_lc, __popc(msk));
                        base = __shfl_sync(0xffffffffu, base, 0);
                        if (pr) {
                            int pos = base + __popc(msk & ((1u << lane) - 1));
                            lk[pos] = (j << 2) | r; lw[pos] = w;
                        }
                    }
                }
                __syncthreads();
            } else {
                // ---- list mode: process frontier directly (no scans)
                if (tid == 0) { s_tc = 0; s_nc = 0; }
                for (int w = tid; w < 256; w += NTHREADS) sbits[w] = 0;
                for (int l = tid; l < cnt; l += NTHREADS) {
                    int e = lk[l];
                    float v = cur[e];
                    Pp[e] += 0.5f * v;
                    lw[l] = v * shh[e >> 2];
                    cur[e] = 0.f;
                }
                __syncthreads();
            }

            // ---- scatter frontier via CSR, record touches
            for (int l = tid; l < cnt; l += NTHREADS) {
                int e = lk[l], k = e >> 2, r = e & 3;
                float w = lw[l];
                int p1 = g_rowptr[k + 1];
                for (int p = g_rowptr[k]; p < p1; p++) {
                    int d = (g_dst[p] << 2) | r;
                    atomicAdd(&cur[d], w);
                    int tp = atomicAdd(&s_tc, 1);
                    if (tp < TCAP) lt[tp] = d;
                }
            }
            __syncthreads();
            int tc = s_tc;
            if (tc > TCAP) { mode = 0; continue; }  // overflow: rebuild by phase A

            // ---- build next frontier from touched entries (bitset dedupe)
            for (int l = tid; l < tc; l += NTHREADS) {
                int e = lt[l];
                if (cur[e] >= RMAXF) {
                    unsigned bit = 1u << (e & 31);
                    unsigned old = atomicOr(&sbits[e >> 5], bit);
                    if (!(old & bit)) {
                        int pos = atomicAdd(&s_nc, 1);
                        if (pos < LISTCAP) lk[pos] = e;
                    }
                }
            }
            __syncthreads();
            int nc = s_nc;
            if (nc == 0) break;
            if (nc > LISTCAP) { mode = 0; }
            else { mode = 1; cnt = nc; }
        }
        __syncthreads();

        // ---- fused top-k per row (256 threads per row, 8 warps)
        const int rg = tid >> 8;     // 0..3
        const int tl = tid & 255;
        for (int q = 0; q < TOPK; q++) {
            float bv = -1.f; int bi = NN;
#pragma unroll
            for (int m = 0; m < NN / 256; m++) {
                int j = tl + 256 * m;
                float v = Pp[(j << 2) | rg];
                if (v > bv || (v == bv && j < bi)) { bv = v; bi = j; }
            }
#pragma unroll
            for (int off = 16; off; off >>= 1) {
                float ov = __shfl_down_sync(0xffffffffu, bv, off);
                int oi = __shfl_down_sync(0xffffffffu, bi, off);
                if (ov > bv || (ov == bv && oi < bi)) { bv = ov; bi = oi; }
            }
            if (lane == 0) { s_redv[wid] = bv; s_redi[wid] = bi; }
            __syncthreads();
            if (tl == 0) {
                float v0 = s_redv[8 * rg]; int i0 = s_redi[8 * rg];
#pragma unroll
                for (int w = 1; w < 8; w++) {
                    float v1 = s_redv[8 * rg + w]; int i1 = s_redi[8 * rg + w];
                    if (v1 > v0 || (v1 == v0 && i1 < i0)) { v0 = v1; i0 = i1; }
                }
                s_tv[rg][q] = v0; s_ti[rg][q] = i0;
                Pp[(i0 << 2) | rg] = -2.f;
            }
            __syncthreads();
        }

        // ---- output GEMV: weights/indices read from shared (low reg pressure)
        const float4* X4 = (const float4*)X;
        float4* out4 = (float4*)out;
#pragma unroll
        for (int m = 0; m < DF / 4 / 256; m++) {
            int col = tl + 256 * m;
            float4 acc = make_float4(0.f, 0.f, 0.f, 0.f);
#pragma unroll
            for (int q = 0; q < TOPK; q++) {
                float w = s_tv[rg][q];
                float4 x = __ldg(&X4[(size_t)s_ti[rg][q] * (DF / 4) + col]);
                acc.x += w * x.x; acc.y += w * x.y;
                acc.z += w * x.z; acc.w += w * x.w;
            }
            out4[(size_t)(row0 + rg) * (DF / 4) + col] = acc;
        }
    }
}

// ---------------- launch ----------------
extern "C" void kernel_launch(void* const* d_in, const int* in_sizes, int n_in,
                              void* d_out, int out_size) {
    const float* X;
    const int* ei;
    if (in_sizes[0] == 2 * NE) { ei = (const int*)d_in[0]; X = (const float*)d_in[1]; }
    else { X = (const float*)d_in[0]; ei = (const int*)d_in[1]; }
    float* out = (float*)d_out;

    const int smem = (3 * ROWS * NN + NN) * sizeof(float)        // pv,cur,Pp,shh
                   + (NN + 4 + TCAP + LISTCAP) * sizeof(int)     // scol,lt,lk
                   + LISTCAP * sizeof(float)                     // lw
                   + 256 * sizeof(unsigned)                      // sbits
                   + NE * sizeof(unsigned short)                 // ssrc
                   + NN * sizeof(unsigned short);                // sperm
    cudaFuncSetAttribute(k_push, cudaFuncAttributeMaxDynamicSharedMemorySize, smem);

    k_zero<<<1, 1024>>>();
    k_count<<<NE / 256, 256>>>(ei);
    k_scan<<<1, 256>>>();
    k_perm<<<1, 256>>>();
    k_fill<<<NE / 256, 256>>>(ei);
    k_sort<<<(2 * NN) / 256, 256>>>();
    k_push<<<GRID, NTHREADS, smem>>>(X, out);
}

// round 9
// speedup vs baseline: 1.3471x; 1.1031x over previous
#include <cuda_runtime.h>

#define NN 2048
#define NE 32768
#define DF 2048
#define TOPK 20
#define RMAXF 1e-5f
#define ROWS 4
#define NTILES 512
#define NTHREADS 512
#define GRID 296
#define LISTCAP 1024
#define SPARSE_T 768
#define MAXIT 500
#define NGRP 64              // 64 groups x 32 columns

// ---------------- device scratch ----------------
__device__ int g_rowptr[NN + 1], g_colptr[NN + 1];
__device__ float g_halfinv[NN];
__device__ int g_dst[NE];        // CSR out-edges (per-row sorted)
__device__ int g_srcCSC[NE];     // CSC in-edges  (per-col sorted)
__device__ int g_perm[NN];       // columns sorted by in-degree (ascending)
__device__ int g_ppos[NN];       // inverse perm
__device__ int g_ellbase[NGRP + 1];          // u16-element offsets
__device__ unsigned short g_ell[262144];     // ELL: [grp][p][lane] = src<<4 (pad=2048<<4)
__device__ int g_work;

// ---------------- setup kernel 1: single block ----------------
__global__ void __launch_bounds__(1024) k_prep(const int* __restrict__ ei) {
    __shared__ int sdeg[NN], sindeg[NN], sfr[NN], sfc[NN];
    __shared__ int s[256];
    __shared__ int hist[64], hbase[64];
    const int t = threadIdx.x;

    if (t == 0) g_work = 0;
    for (int k = t; k < NN; k += 1024) { sdeg[k] = 0; sindeg[k] = 0; sfr[k] = 0; sfc[k] = 0; }
    if (t < 64) hist[t] = 0;
    __syncthreads();

    for (int e = t; e < NE; e += 1024) {
        atomicAdd(&sdeg[ei[e]], 1);
        atomicAdd(&sindeg[ei[NE + e]], 1);
    }
    __syncthreads();

    // prefix scans: every barrier executed by ALL threads
    for (int pass = 0; pass < 2; pass++) {
        const int* cnt = pass ? sdeg : sindeg;
        int* ptr = pass ? g_rowptr : g_colptr;
        int v[8]; int sum = 0; const int base = t * 8;
        if (t < 256) {
#pragma unroll
            for (int m = 0; m < 8; m++) { v[m] = cnt[base + m]; sum += v[m]; }
            s[t] = sum;
        }
        __syncthreads();
        for (int off = 1; off < 256; off <<= 1) {
            int x = 0;
            if (t < 256 && t >= off) x = s[t - off];
            __syncthreads();
            if (t < 256) s[t] += x;
            __syncthreads();
        }
        if (t < 256) {
            int excl = (t == 0) ? 0 : s[t - 1];
#pragma unroll
            for (int m = 0; m < 8; m++) { ptr[base + m] = excl; excl += v[m]; }
            if (t == 255) ptr[NN] = excl;
        }
        __syncthreads();
    }

    // halfinv + degree histogram
    for (int k = t; k < NN; k += 1024) {
        int d = sdeg[k];
        g_halfinv[k] = 0.5f / (d ? (float)d : 1.f);
        atomicAdd(&hist[min(sindeg[k], 63)], 1);
    }
    __syncthreads();
    if (t == 0) { int acc = 0; for (int b = 0; b < 64; b++) { hbase[b] = acc; acc += hist[b]; } }
    __syncthreads();
    for (int k = t; k < NN; k += 1024) {
        int pos = atomicAdd(&hbase[min(sindeg[k], 63)], 1);
        g_perm[pos] = k;
        g_ppos[k] = pos;
    }
    __syncthreads();

    // ELL group bases (ascending degree => group max = last member's indeg)
    if (t == 0) {
        int acc = 0;
        for (int g = 0; g < NGRP; g++) {
            g_ellbase[g] = acc;
            acc += 32 * sindeg[g_perm[g * 32 + 31]];
        }
        g_ellbase[NGRP] = acc;
    }

    // fill CSR/CSC
    for (int e = t; e < NE; e += 1024) {
        int r = ei[e], c = ei[NE + e];
        int pr = atomicAdd(&sfr[r], 1);
        g_dst[g_rowptr[r] + pr] = c;
        int pc = atomicAdd(&sfc[c], 1);
        g_srcCSC[g_colptr[c] + pc] = r;
    }
}

// ---------------- setup kernel 2: sort lists + ELL fill ----------------
__global__ void k_build() {
    int id = blockIdx.x * blockDim.x + threadIdx.x;
    if (id >= 2 * NN) return;
    if (id < NN) {
        // sort CSC list of column id, then fill its ELL slot
        int p0 = g_colptr[id], p1 = g_colptr[id + 1];
        for (int i = p0 + 1; i < p1; i++) {
            int x = g_srcCSC[i]; int j = i - 1;
            while (j >= p0 && g_srcCSC[j] > x) { g_srcCSC[j + 1] = g_srcCSC[j]; j--; }
            g_srcCSC[j + 1] = x;
        }
        int deg = p1 - p0;
        int pos = g_ppos[id];
        int g = pos >> 5, l = pos & 31;
        int base = g_ellbase[g];
        int gm = (g_ellbase[g + 1] - base) >> 5;
        for (int p = 0; p < gm; p++)
            g_ell[base + (p << 5) + l] =
                (p < deg) ? (unsigned short)(g_srcCSC[p0 + p] << 4)
                          : (unsigned short)(2048 << 4);
    } else {
        // sort CSR list of row id-NN
        int r = id - NN;
        int p0 = g_rowptr[r], p1 = g_rowptr[r + 1];
        for (int i = p0 + 1; i < p1; i++) {
            int x = g_dst[i]; int j = i - 1;
            while (j >= p0 && g_dst[j] > x) { g_dst[j + 1] = g_dst[j]; j--; }
            g_dst[j + 1] = x;
        }
    }
}

// ---------------- persistent push + fused topk/output ----------------
__global__ void __launch_bounds__(NTHREADS, 2)
k_push(const float* __restrict__ X, float* __restrict__ out) {
    extern __shared__ float sh[];
    float* pv = sh;                      // [8196] masked push*(0.5/deg); [8192..8195]=0 pad
    float* cur = pv + ROWS * NN + 4;     // [8192] residual
    float* Pp = cur + ROWS * NN;         // [8192] P accumulator
    int* lk = (int*)(Pp + ROWS * NN);    // [LISTCAP] frontier entries
    __shared__ int s_cnt, s_lc, s_tile;
    __shared__ float s_redv[16];
    __shared__ int s_redi[16];
    __shared__ float s_tv[ROWS][TOPK];
    __shared__ int s_ti[ROWS][TOPK];

    float4* pv4 = (float4*)pv;
    float4* cur4 = (float4*)cur;
    float4* Pp4 = (float4*)Pp;

    const int tid = threadIdx.x;
    const int lane = tid & 31;
    const int wid = tid >> 5;

    while (true) {
        __syncthreads();
        if (tid == 0) s_tile = atomicAdd(&g_work, 1);
        __syncthreads();
        const int t = s_tile;
        if (t >= NTILES) break;
        const int row0 = t * ROWS;

        // ---- init tile state
        if (tid == 0) pv4[2048] = make_float4(0.f, 0.f, 0.f, 0.f);  // ELL pad target
#pragma unroll
        for (int m = 0; m < NN / NTHREADS; m++) {
            int j = tid + NTHREADS * m;
            float4 z = make_float4(0.f, 0.f, 0.f, 0.f);
            Pp4[j] = z;
            int d = j - row0;
            if (d >= 0 && d < ROWS) ((float*)&z)[d] = 1.f;
            cur4[j] = z;
        }

        for (int iter = 0; iter < MAXIT; iter++) {
            if (tid == 0) { s_cnt = 0; s_lc = 0; }
            __syncthreads();

            // ---- phase A: mask, write pv, update P, zero pushed, count
            int c = 0;
#pragma unroll
            for (int m = 0; m < NN / NTHREADS; m++) {
                int j = tid + NTHREADS * m;
                float4 v = cur4[j];
                float h = __ldg(&g_halfinv[j]);
                bool px = v.x >= RMAXF, py = v.y >= RMAXF,
                     pz = v.z >= RMAXF, pw = v.w >= RMAXF;
                pv4[j] = make_float4(px ? v.x * h : 0.f, py ? v.y * h : 0.f,
                                     pz ? v.z * h : 0.f, pw ? v.w * h : 0.f);
                if (px | py | pz | pw) {
                    float4 p = Pp4[j];
                    if (px) { p.x += 0.5f * v.x; v.x = 0.f; c++; }
                    if (py) { p.y += 0.5f * v.y; v.y = 0.f; c++; }
                    if (pz) { p.z += 0.5f * v.z; v.z = 0.f; c++; }
                    if (pw) { p.w += 0.5f * v.w; v.w = 0.f; c++; }
                    Pp4[j] = p;
                    cur4[j] = v;
                }
            }
            c = __reduce_add_sync(0xffffffffu, c);
            if (lane == 0 && c) atomicAdd(&s_cnt, c);
            __syncthreads();
            const int cnt = s_cnt;
            if (cnt == 0) break;

            if (cnt > SPARSE_T) {
                // ---- dense: ELL gather, coalesced LDG.U16 index + LDS.128 pv
#pragma unroll
                for (int m = 0; m < NGRP / (NTHREADS / 32); m++) {
                    int g = wid + (NTHREADS / 32) * m;
                    int jr = __ldg(&g_perm[(g << 5) + lane]);
                    int base = __ldg(&g_ellbase[g]);
                    int gm = (__ldg(&g_ellbase[g + 1]) - base) >> 5;
                    const unsigned short* ep = g_ell + base + lane;
                    float4 acc = cur4[jr];
#pragma unroll 4
                    for (int p = 0; p < gm; p++) {
                        int off = ep[p << 5];
                        float4 v = *(const float4*)((const char*)pv + off);
                        acc.x += v.x; acc.y += v.y; acc.z += v.z; acc.w += v.w;
                    }
                    cur4[jr] = acc;
                }
                __syncthreads();
            } else {
                // ---- sparse: compact frontier from pv, CSR scatter
#pragma unroll
                for (int m = 0; m < NN / NTHREADS; m++) {
                    int j = tid + NTHREADS * m;
                    float4 v = pv4[j];
#pragma unroll
                    for (int r = 0; r < 4; r++) {
                        bool pr = ((float*)&v)[r] > 0.f;
                        unsigned msk = __ballot_sync(0xffffffffu, pr);
                        int base = 0;
                        if (lane == 0 && msk) base = atomicAdd(&s_lc, __popc(msk));
                        base = __shfl_sync(0xffffffffu, base, 0);
                        if (pr) {
                            int pos = base + __popc(msk & ((1u << lane) - 1));
                            if (pos < LISTCAP) lk[pos] = (j << 2) | r;
                        }
                    }
                }
                __syncthreads();
                for (int l = tid; l < cnt; l += NTHREADS) {
                    int e = lk[l], k = e >> 2, r = e & 3;
                    float w = pv[e];
                    int p1 = __ldg(&g_rowptr[k + 1]);
                    for (int p = __ldg(&g_rowptr[k]); p < p1; p++)
                        atomicAdd(&cur[(__ldg(&g_dst[p]) << 2) | r], w);
                }
                __syncthreads();
            }
        }
        __syncthreads();

        // ---- fused top-k per row (128 threads per row)
        const int rg = tid >> 7;
        const int tl = tid & 127;
        for (int q = 0; q < TOPK; q++) {
            float bv = -1.f; int bi = NN;
#pragma unroll
            for (int m = 0; m < NN / 128; m++) {
                int j = tl + 128 * m;
                float v = Pp[(j << 2) | rg];
                if (v > bv || (v == bv && j < bi)) { bv = v; bi = j; }
            }
#pragma unroll
            for (int off = 16; off; off >>= 1) {
                float ov = __shfl_down_sync(0xffffffffu, bv, off);
                int oi = __shfl_down_sync(0xffffffffu, bi, off);
                if (ov > bv || (ov == bv && oi < bi)) { bv = ov; bi = oi; }
            }
            if (lane == 0) { s_redv[wid] = bv; s_redi[wid] = bi; }
            __syncthreads();
            if (tl == 0) {
                float v0 = s_redv[4 * rg]; int i0 = s_redi[4 * rg];
#pragma unroll
                for (int w = 1; w < 4; w++) {
                    float v1 = s_redv[4 * rg + w]; int i1 = s_redi[4 * rg + w];
                    if (v1 > v0 || (v1 == v0 && i1 < i0)) { v0 = v1; i0 = i1; }
                }
                s_tv[rg][q] = v0; s_ti[rg][q] = i0;
                Pp[(i0 << 2) | rg] = -2.f;
            }
            __syncthreads();
        }

        // ---- output GEMV
        const float4* X4 = (const float4*)X;
        float4* out4 = (float4*)out;
#pragma unroll
        for (int m = 0; m < DF / 4 / 128; m++) {
            int col = tl + 128 * m;
            float4 acc = make_float4(0.f, 0.f, 0.f, 0.f);
#pragma unroll
            for (int q = 0; q < TOPK; q++) {
                float w = s_tv[rg][q];
                float4 x = __ldg(&X4[(size_t)s_ti[rg][q] * (DF / 4) + col]);
                acc.x += w * x.x; acc.y += w * x.y;
                acc.z += w * x.z; acc.w += w * x.w;
            }
            out4[(size_t)(row0 + rg) * (DF / 4) + col] = acc;
        }
    }
}

// ---------------- launch ----------------
extern "C" void kernel_launch(void* const* d_in, const int* in_sizes, int n_in,
                              void* d_out, int out_size) {
    const float* X;
    const int* ei;
    if (in_sizes[0] == 2 * NE) { ei = (const int*)d_in[0]; X = (const float*)d_in[1]; }
    else { X = (const float*)d_in[0]; ei = (const int*)d_in[1]; }
    float* out = (float*)d_out;

    const int smem = (ROWS * NN + 4 + 2 * ROWS * NN) * sizeof(float)
                   + LISTCAP * sizeof(int);   // ~102.4 KB -> 2 CTAs/SM
    cudaFuncSetAttribute(k_push, cudaFuncAttributeMaxDynamicSharedMemorySize, smem);

    k_prep<<<1, 1024>>>(ei);
    k_build<<<16, 256>>>();
    k_push<<<GRID, NTHREADS, smem>>>(X, out);
}

// round 10
// speedup vs baseline: 1.5347x; 1.1392x over previous
#include <cuda_runtime.h>

#define NN 2048
#define NE 32768
#define DF 2048
#define TOPK 20
#define RMAXF 1e-5f
#define ROWS 4
#define NTILES 512
#define NTHREADS 512
#define GRID 296
#define LISTCAP 1024
#define SPARSE_T 768
#define MAXIT 500
#define NGRP 64              // 64 groups x 32 columns

// ---------------- device scratch ----------------
__device__ int g_deg[NN], g_indeg[NN];
__device__ int g_rowptr[NN + 1], g_colptr[NN + 1];
__device__ int g_fillr[NN], g_fillc[NN];
__device__ float g_halfinv[NN];
__device__ int g_dst[NE];        // CSR out-edges (per-row sorted)
__device__ int g_srcCSC[NE];     // CSC in-edges  (per-col sorted)
__device__ int g_perm[NN];       // columns sorted by in-degree (ascending)
__device__ int g_ppos[NN];       // inverse perm
__device__ int g_ellbase[NGRP + 1];
__device__ unsigned short g_ell[262144];   // [grp][p][lane] = src<<4 (pad=2048<<4)
__device__ int g_work;

// ---------------- setup (5 launches; #6 = k_push for ncu -s 5) ----------------
__global__ void k_zero() {
    int i = blockIdx.x * 256 + threadIdx.x;
    if (i < NN) { g_deg[i] = 0; g_indeg[i] = 0; g_fillr[i] = 0; g_fillc[i] = 0; }
    if (i == 0) g_work = 0;
}

__global__ void k_count(const int* __restrict__ ei) {
    int e = blockIdx.x * 256 + threadIdx.x;
    if (e >= NE) return;
    atomicAdd(&g_deg[ei[e]], 1);
    atomicAdd(&g_indeg[ei[NE + e]], 1);
}

__global__ void __launch_bounds__(256) k_scanperm() {
    __shared__ int s[256];
    __shared__ int hist[64], hb[64];
    const int t = threadIdx.x;
    if (t < 64) hist[t] = 0;
    for (int pass = 0; pass < 2; pass++) {
        const int* cnt = pass ? g_deg : g_indeg;
        int* ptr = pass ? g_rowptr : g_colptr;
        int base = t * 8;
        int v[8]; int sum = 0;
#pragma unroll
        for (int m = 0; m < 8; m++) { v[m] = cnt[base + m]; sum += v[m]; }
        s[t] = sum; __syncthreads();
        for (int off = 1; off < 256; off <<= 1) {
            int x = (t >= off) ? s[t - off] : 0;
            __syncthreads();
            s[t] += x;
            __syncthreads();
        }
        int excl = (t == 0) ? 0 : s[t - 1];
#pragma unroll
        for (int m = 0; m < 8; m++) { ptr[base + m] = excl; excl += v[m]; }
        if (t == 255) ptr[NN] = excl;
        __syncthreads();
    }
    // halfinv + degree histogram
    for (int k = t; k < NN; k += 256) {
        int d = g_deg[k];
        g_halfinv[k] = 0.5f / (d ? (float)d : 1.f);
        atomicAdd(&hist[min(g_indeg[k], 63)], 1);
    }
    __syncthreads();
    if (t == 0) { int acc = 0; for (int b = 0; b < 64; b++) { hb[b] = acc; acc += hist[b]; } }
    __syncthreads();
    for (int k = t; k < NN; k += 256) {
        int pos = atomicAdd(&hb[min(g_indeg[k], 63)], 1);
        g_perm[pos] = k;
        g_ppos[k] = pos;
    }
    __syncthreads();
    if (t == 0) {
        int acc = 0;
        for (int g = 0; g < NGRP; g++) {
            g_ellbase[g] = acc;
            acc += 32 * g_indeg[g_perm[g * 32 + 31]];
        }
        g_ellbase[NGRP] = acc;
    }
}

__global__ void k_fill(const int* __restrict__ ei) {
    int e = blockIdx.x * 256 + threadIdx.x;
    if (e >= NE) return;
    int r = ei[e], c = ei[NE + e];
    int pr = atomicAdd(&g_fillr[r], 1);
    g_dst[g_rowptr[r] + pr] = c;
    int pc = atomicAdd(&g_fillc[c], 1);
    g_srcCSC[g_colptr[c] + pc] = r;
}

__global__ void k_build() {
    int id = blockIdx.x * blockDim.x + threadIdx.x;
    if (id >= 2 * NN) return;
    if (id < NN) {
        int p0 = g_colptr[id], p1 = g_colptr[id + 1];
        for (int i = p0 + 1; i < p1; i++) {
            int x = g_srcCSC[i]; int j = i - 1;
            while (j >= p0 && g_srcCSC[j] > x) { g_srcCSC[j + 1] = g_srcCSC[j]; j--; }
            g_srcCSC[j + 1] = x;
        }
        int deg = p1 - p0;
        int pos = g_ppos[id];
        int g = pos >> 5, l = pos & 31;
        int base = g_ellbase[g];
        int gm = (g_ellbase[g + 1] - base) >> 5;
        for (int p = 0; p < gm; p++)
            g_ell[base + (p << 5) + l] =
                (p < deg) ? (unsigned short)(g_srcCSC[p0 + p] << 4)
                          : (unsigned short)(2048 << 4);
    } else {
        int r = id - NN;
        int p0 = g_rowptr[r], p1 = g_rowptr[r + 1];
        for (int i = p0 + 1; i < p1; i++) {
            int x = g_dst[i]; int j = i - 1;
            while (j >= p0 && g_dst[j] > x) { g_dst[j + 1] = g_dst[j]; j--; }
            g_dst[j + 1] = x;
        }
    }
}

// ---------------- persistent push + fused topk/output ----------------
__global__ void __launch_bounds__(NTHREADS, 2)
k_push(const float* __restrict__ X, float* __restrict__ out) {
    extern __shared__ float sh[];
    float* pv = sh;                      // [8196] masked push*(0.5/deg); [8192..]=0 pad
    float* cur = pv + ROWS * NN + 4;     // [8192] residual
    float* Pp = cur + ROWS * NN;         // [8192] P accumulator
    float* shh = Pp + ROWS * NN;         // [2048] 0.5/deg
    int* lk = (int*)(shh + NN);          // [LISTCAP] frontier entries
    __shared__ int s_cnt, s_lc, s_tile;
    __shared__ float s_redv[16];
    __shared__ int s_redi[16];
    __shared__ float s_tv[ROWS][TOPK];
    __shared__ int s_ti[ROWS][TOPK];

    float4* pv4 = (float4*)pv;
    float4* cur4 = (float4*)cur;
    float4* Pp4 = (float4*)Pp;

    const int tid = threadIdx.x;
    const int lane = tid & 31;
    const int wid = tid >> 5;

    for (int k = tid; k < NN; k += NTHREADS) shh[k] = g_halfinv[k];

    while (true) {
        __syncthreads();
        if (tid == 0) s_tile = atomicAdd(&g_work, 1);
        __syncthreads();
        const int t = s_tile;
        if (t >= NTILES) break;
        const int row0 = t * ROWS;

        // ---- init tile state
        if (tid == 0) pv4[2048] = make_float4(0.f, 0.f, 0.f, 0.f);  // ELL pad target
#pragma unroll
        for (int m = 0; m < NN / NTHREADS; m++) {
            int j = tid + NTHREADS * m;
            float4 z = make_float4(0.f, 0.f, 0.f, 0.f);
            Pp4[j] = z;
            int d = j - row0;
            if (d >= 0 && d < ROWS) ((float*)&z)[d] = 1.f;
            cur4[j] = z;
        }

        for (int iter = 0; iter < MAXIT; iter++) {
            if (tid == 0) { s_cnt = 0; s_lc = 0; }
            __syncthreads();

            // ---- phase A: mask, write pv, update P, zero pushed, count,
            //      AND compact frontier inline (ballot per row-slot)
            int c = 0;
#pragma unroll
            for (int m = 0; m < NN / NTHREADS; m++) {
                int j = tid + NTHREADS * m;
                float4 v = cur4[j];
                float h = shh[j];
                bool px = v.x >= RMAXF, py = v.y >= RMAXF,
                     pz = v.z >= RMAXF, pw = v.w >= RMAXF;
                pv4[j] = make_float4(px ? v.x * h : 0.f, py ? v.y * h : 0.f,
                                     pz ? v.z * h : 0.f, pw ? v.w * h : 0.f);
                if (px | py | pz | pw) {
                    float4 p = Pp4[j];
                    if (px) { p.x += 0.5f * v.x; v.x = 0.f; c++; }
                    if (py) { p.y += 0.5f * v.y; v.y = 0.f; c++; }
                    if (pz) { p.z += 0.5f * v.z; v.z = 0.f; c++; }
                    if (pw) { p.w += 0.5f * v.w; v.w = 0.f; c++; }
                    Pp4[j] = p;
                    cur4[j] = v;
                }
                // inline frontier compaction (warp-uniform control flow)
                bool pr[4] = {px, py, pz, pw};
#pragma unroll
                for (int r = 0; r < 4; r++) {
                    unsigned msk = __ballot_sync(0xffffffffu, pr[r]);
                    if (msk) {
                        int base = 0;
                        if (lane == 0) base = atomicAdd(&s_lc, __popc(msk));
                        base = __shfl_sync(0xffffffffu, base, 0);
                        if (pr[r]) {
                            int pos = base + __popc(msk & ((1u << lane) - 1));
                            if (pos < LISTCAP) lk[pos] = (j << 2) | r;
                        }
                    }
                }
            }
            c = __reduce_add_sync(0xffffffffu, c);
            if (lane == 0 && c) atomicAdd(&s_cnt, c);
            __syncthreads();
            const int cnt = s_cnt;
            if (cnt == 0) break;

            if (cnt > SPARSE_T) {
                // ---- dense: ELL gather, coalesced LDG.U16 index + LDS.128 pv
#pragma unroll
                for (int m = 0; m < NGRP / (NTHREADS / 32); m++) {
                    int g = wid + (NTHREADS / 32) * m;
                    int jr = __ldg(&g_perm[(g << 5) + lane]);
                    int base = __ldg(&g_ellbase[g]);
                    int gm = (__ldg(&g_ellbase[g + 1]) - base) >> 5;
                    const unsigned short* ep = g_ell + base + lane;
                    float4 acc = cur4[jr];
#pragma unroll 4
                    for (int p = 0; p < gm; p++) {
                        int off = ep[p << 5];
                        float4 v = *(const float4*)((const char*)pv + off);
                        acc.x += v.x; acc.y += v.y; acc.z += v.z; acc.w += v.w;
                    }
                    cur4[jr] = acc;
                }
                __syncthreads();
            } else {
                // ---- sparse: CSR scatter of pre-built frontier
                for (int l = tid; l < cnt; l += NTHREADS) {
                    int e = lk[l], k = e >> 2, r = e & 3;
                    float w = pv[e];
                    int p1 = __ldg(&g_rowptr[k + 1]);
                    for (int p = __ldg(&g_rowptr[k]); p < p1; p++)
                        atomicAdd(&cur[(__ldg(&g_dst[p]) << 2) | r], w);
                }
                __syncthreads();
            }
        }
        __syncthreads();

        // ---- fused top-k per row (128 threads per row)
        const int rg = tid >> 7;
        const int tl = tid & 127;
        for (int q = 0; q < TOPK; q++) {
            float bv = -1.f; int bi = NN;
#pragma unroll
            for (int m = 0; m < NN / 128; m++) {
                int j = tl + 128 * m;
                float v = Pp[(j << 2) | rg];
                if (v > bv || (v == bv && j < bi)) { bv = v; bi = j; }
            }
#pragma unroll
            for (int off = 16; off; off >>= 1) {
                float ov = __shfl_down_sync(0xffffffffu, bv, off);
                int oi = __shfl_down_sync(0xffffffffu, bi, off);
                if (ov > bv || (ov == bv && oi < bi)) { bv = ov; bi = oi; }
            }
            if (lane == 0) { s_redv[wid] = bv; s_redi[wid] = bi; }
            __syncthreads();
            if (tl == 0) {
                float v0 = s_redv[4 * rg]; int i0 = s_redi[4 * rg];
#pragma unroll
                for (int w = 1; w < 4; w++) {
                    float v1 = s_redv[4 * rg + w]; int i1 = s_redi[4 * rg + w];
                    if (v1 > v0 || (v1 == v0 && i1 < i0)) { v0 = v1; i0 = i1; }
                }
                s_tv[rg][q] = v0; s_ti[rg][q] = i0;
                Pp[(i0 << 2) | rg] = -2.f;
            }
            __syncthreads();
        }

        // ---- output GEMV
        const float4* X4 = (const float4*)X;
        float4* out4 = (float4*)out;
#pragma unroll
        for (int m = 0; m < DF / 4 / 128; m++) {
            int col = tl + 128 * m;
            float4 acc = make_float4(0.f, 0.f, 0.f, 0.f);
#pragma unroll
            for (int q = 0; q < TOPK; q++) {
                float w = s_tv[rg][q];
                float4 x = __ldg(&X4[(size_t)s_ti[rg][q] * (DF / 4) + col]);
                acc.x += w * x.x; acc.y += w * x.y;
                acc.z += w * x.z; acc.w += w * x.w;
            }
            out4[(size_t)(row0 + rg) * (DF / 4) + col] = acc;
        }
    }
}

// ---------------- launch ----------------
extern "C" void kernel_launch(void* const* d_in, const int* in_sizes, int n_in,
                              void* d_out, int out_size) {
    const float* X;
    const int* ei;
    if (in_sizes[0] == 2 * NE) { ei = (const int*)d_in[0]; X = (const float*)d_in[1]; }
    else { X = (const float*)d_in[0]; ei = (const int*)d_in[1]; }
    float* out = (float*)d_out;

    const int smem = (ROWS * NN + 4 + 2 * ROWS * NN + NN) * sizeof(float)
                   + LISTCAP * sizeof(int);   // ~110.6 KB -> 2 CTAs/SM
    cudaFuncSetAttribute(k_push, cudaFuncAttributeMaxDynamicSharedMemorySize, smem);

    k_zero<<<(NN + 255) / 256, 256>>>();
    k_count<<<NE / 256, 256>>>(ei);
    k_scanperm<<<1, 256>>>();
    k_fill<<<NE / 256, 256>>>(ei);
    k_build<<<16, 256>>>();
    k_push<<<GRID, NTHREADS, smem>>>(X, out);
}